// round 9
// baseline (speedup 1.0000x reference)
#include <cuda_runtime.h>
#include <cstdint>
#include <math.h>

#define Ee 768
#define Hh 12
#define Dd 64
#define Bb 8
#define Nn 1024
#define Mtot (Bb * Nn)   // 8192

// Scratch (static device globals; allocation is forbidden)
__device__ float g_q[(size_t)Mtot * Ee];
__device__ float g_k[(size_t)Mtot * Ee];
__device__ float g_v[(size_t)Mtot * Ee];
__device__ float g_attn[(size_t)Mtot * Ee];

// ======================= helpers ===========================================
__device__ __forceinline__ uint32_t f2tf32(float f) {
    uint32_t r;
    asm("cvt.rna.tf32.f32 %0, %1;" : "=r"(r) : "f"(f));
    return r;
}
__device__ __forceinline__ float f2tf32f(float f) {
    return __uint_as_float(f2tf32(f));
}

__device__ __forceinline__ void mma_tf32(float* d, const uint32_t* a, const uint32_t* b) {
    asm volatile(
        "mma.sync.aligned.m16n8k8.row.col.f32.tf32.tf32.f32 "
        "{%0,%1,%2,%3}, {%4,%5,%6,%7}, {%8,%9}, {%0,%1,%2,%3};"
        : "+f"(d[0]), "+f"(d[1]), "+f"(d[2]), "+f"(d[3])
        : "r"(a[0]), "r"(a[1]), "r"(a[2]), "r"(a[3]), "r"(b[0]), "r"(b[1]));
}

// Interleaved k-position: pairs (k, k+4) land adjacent.
// pos(k) = (k & ~7) + 2*(k & 3) + ((k & 4) >> 2)

// ======================= tf32 tensor-core GEMM =============================
// C[M,Nc] = (A[M,K] @ W[Nc,K]^T + bias) * scale   (torch-style weights)
// CTA 128x128, BK=16, 256 threads (8 warps, 2(m) x 4(n), warp = 64x32).
// Smem rows store k in pair-interleaved order -> fragment loads are LDS.64.
#define BM 128
#define BN 128
#define BKt 16
#define PITCH 20

__global__ __launch_bounds__(256)
void gemm_mma(const float* __restrict__ A, const float* __restrict__ W,
              const float* __restrict__ bias, float* __restrict__ C,
              int M, int Nc, int K, float scale)
{
    __shared__ float As[2][BM][PITCH];
    __shared__ float Bs[2][BN][PITCH];

    const int tid  = threadIdx.x;
    const int lane = tid & 31;
    const int w    = tid >> 5;
    const int wr   = w & 1;
    const int wc   = w >> 1;
    const int rowBase = blockIdx.y * BM;
    const int colBase = blockIdx.x * BN;

    float acc[4][4][4];
    #pragma unroll
    for (int i = 0; i < 4; i++)
        #pragma unroll
        for (int j = 0; j < 4; j++)
            #pragma unroll
            for (int q = 0; q < 4; q++) acc[i][j][q] = 0.f;

    const int lm0 = tid >> 2;
    const int lkq = (tid & 3) * 4;                    // 0,4,8,12
    const int wbase = (lkq & 8) + ((lkq & 4) >> 2);   // interleave base for writer

    const float* Ag0 = A + (size_t)(rowBase + lm0)      * K + lkq;
    const float* Ag1 = A + (size_t)(rowBase + lm0 + 64) * K + lkq;
    const float* Wg0 = W + (size_t)(colBase + lm0)      * K + lkq;
    const float* Wg1 = W + (size_t)(colBase + lm0 + 64) * K + lkq;

    float4 ra0, ra1, rb0, rb1;
    const int NSTEP = K / BKt;   // 48

    ra0 = *(const float4*)(Ag0);
    ra1 = *(const float4*)(Ag1);
    rb0 = *(const float4*)(Wg0);
    rb1 = *(const float4*)(Wg1);
    {
        As[0][lm0     ][wbase + 0] = f2tf32f(ra0.x);
        As[0][lm0     ][wbase + 2] = f2tf32f(ra0.y);
        As[0][lm0     ][wbase + 4] = f2tf32f(ra0.z);
        As[0][lm0     ][wbase + 6] = f2tf32f(ra0.w);
        As[0][lm0 + 64][wbase + 0] = f2tf32f(ra1.x);
        As[0][lm0 + 64][wbase + 2] = f2tf32f(ra1.y);
        As[0][lm0 + 64][wbase + 4] = f2tf32f(ra1.z);
        As[0][lm0 + 64][wbase + 6] = f2tf32f(ra1.w);
        Bs[0][lm0     ][wbase + 0] = f2tf32f(rb0.x);
        Bs[0][lm0     ][wbase + 2] = f2tf32f(rb0.y);
        Bs[0][lm0     ][wbase + 4] = f2tf32f(rb0.z);
        Bs[0][lm0     ][wbase + 6] = f2tf32f(rb0.w);
        Bs[0][lm0 + 64][wbase + 0] = f2tf32f(rb1.x);
        Bs[0][lm0 + 64][wbase + 2] = f2tf32f(rb1.y);
        Bs[0][lm0 + 64][wbase + 4] = f2tf32f(rb1.z);
        Bs[0][lm0 + 64][wbase + 6] = f2tf32f(rb1.w);
    }
    ra0 = *(const float4*)(Ag0 + BKt);
    ra1 = *(const float4*)(Ag1 + BKt);
    rb0 = *(const float4*)(Wg0 + BKt);
    rb1 = *(const float4*)(Wg1 + BKt);

    const int mrow = wr * 64 + (lane >> 2);
    const int ncol = wc * 32 + (lane >> 2);
    const int klo  = lane & 3;

    for (int c = 0; c < NSTEP; c++) {
        __syncthreads();
        int cur = c & 1, nxt = cur ^ 1;

        if (c + 1 < NSTEP) {
            As[nxt][lm0     ][wbase + 0] = f2tf32f(ra0.x);
            As[nxt][lm0     ][wbase + 2] = f2tf32f(ra0.y);
            As[nxt][lm0     ][wbase + 4] = f2tf32f(ra0.z);
            As[nxt][lm0     ][wbase + 6] = f2tf32f(ra0.w);
            As[nxt][lm0 + 64][wbase + 0] = f2tf32f(ra1.x);
            As[nxt][lm0 + 64][wbase + 2] = f2tf32f(ra1.y);
            As[nxt][lm0 + 64][wbase + 4] = f2tf32f(ra1.z);
            As[nxt][lm0 + 64][wbase + 6] = f2tf32f(ra1.w);
            Bs[nxt][lm0     ][wbase + 0] = f2tf32f(rb0.x);
            Bs[nxt][lm0     ][wbase + 2] = f2tf32f(rb0.y);
            Bs[nxt][lm0     ][wbase + 4] = f2tf32f(rb0.z);
            Bs[nxt][lm0     ][wbase + 6] = f2tf32f(rb0.w);
            Bs[nxt][lm0 + 64][wbase + 0] = f2tf32f(rb1.x);
            Bs[nxt][lm0 + 64][wbase + 2] = f2tf32f(rb1.y);
            Bs[nxt][lm0 + 64][wbase + 4] = f2tf32f(rb1.z);
            Bs[nxt][lm0 + 64][wbase + 6] = f2tf32f(rb1.w);
        }
        if (c + 2 < NSTEP) {
            int off = (c + 2) * BKt;
            ra0 = *(const float4*)(Ag0 + off);
            ra1 = *(const float4*)(Ag1 + off);
            rb0 = *(const float4*)(Wg0 + off);
            rb1 = *(const float4*)(Wg1 + off);
        }

        #pragma unroll
        for (int ks = 0; ks < BKt; ks += 8) {
            uint32_t af[4][4], bf[4][2];
            #pragma unroll
            for (int mf = 0; mf < 4; mf++) {
                uint2 u0 = *(const uint2*)&As[cur][mrow + mf * 16    ][ks + 2 * klo];
                uint2 u1 = *(const uint2*)&As[cur][mrow + mf * 16 + 8][ks + 2 * klo];
                af[mf][0] = u0.x; af[mf][2] = u0.y;
                af[mf][1] = u1.x; af[mf][3] = u1.y;
            }
            #pragma unroll
            for (int nf = 0; nf < 4; nf++) {
                uint2 ub = *(const uint2*)&Bs[cur][ncol + nf * 8][ks + 2 * klo];
                bf[nf][0] = ub.x; bf[nf][1] = ub.y;
            }
            #pragma unroll
            for (int mf = 0; mf < 4; mf++)
                #pragma unroll
                for (int nf = 0; nf < 4; nf++)
                    mma_tf32(acc[mf][nf], af[mf], bf[nf]);
        }
    }

    #pragma unroll
    for (int mf = 0; mf < 4; mf++) {
        int r0 = rowBase + wr * 64 + mf * 16 + (lane >> 2);
        #pragma unroll
        for (int nf = 0; nf < 4; nf++) {
            int c0 = colBase + wc * 32 + nf * 8 + (lane & 3) * 2;
            float b0 = bias[c0], b1 = bias[c0 + 1];
            float2 lo, hi;
            lo.x = (acc[mf][nf][0] + b0) * scale;
            lo.y = (acc[mf][nf][1] + b1) * scale;
            hi.x = (acc[mf][nf][2] + b0) * scale;
            hi.y = (acc[mf][nf][3] + b1) * scale;
            *(float2*)&C[(size_t)r0 * Nc + c0]       = lo;
            *(float2*)&C[(size_t)(r0 + 8) * Nc + c0] = hi;
        }
    }
}

// ---------------------------------------------------------------------------
// Flash attention via mma.sync tf32, pair-interleaved Q/K/P smem rows.
// CTA: 128 q-rows x (h,b); k-tile 64; 8 warps as 4(m) x 2(n); warp tile 32x32.
// ---------------------------------------------------------------------------
#define QP 68
#define VPIT 72
#define QS_OFF 0
#define KP_OFF2 (128 * QP)            // 8704
#define VS_OFF2 (KP_OFF2 + 128 * QP)  // 17408
#define ST_OFF  (VS_OFF2 + 64 * VPIT) // 22016
#define ATTN_SMEM ((ST_OFF + 512) * 4)  // 90112 bytes

__global__ __launch_bounds__(256, 2)
void attn_mma(const float* __restrict__ abias)
{
    extern __shared__ float sm[];
    float* Qs = sm + QS_OFF;
    float* KP = sm + KP_OFF2;
    float* Vs = sm + VS_OFF2;
    float* stMax = sm + ST_OFF;        // [128][2]
    float* stSum = sm + ST_OFF + 256;  // [128][2]

    const int tid  = threadIdx.x;
    const int lane = tid & 31;
    const int w    = tid >> 5;
    const int ms   = (w & 3) * 32;
    const int nsi  = w >> 2;
    const int ns   = nsi * 32;
    const int lr   = lane >> 2;
    const int lc   = lane & 3;

    const int q0 = blockIdx.x * 128;
    const int h  = blockIdx.y;
    const int b  = blockIdx.z;

    const float* qg = g_q + ((size_t)b * Nn + q0) * Ee + h * Dd;
    const float* kg = g_k + (size_t)b * Nn * Ee + h * Dd;
    const float* vg = g_v + (size_t)b * Nn * Ee + h * Dd;
    const float* bg = abias + (((size_t)b * Hh + h) * Nn + q0) * Nn;

    // Load Q once (tf32-rounded), rows pair-interleaved over d
    #pragma unroll
    for (int it = 0; it < 8; it++) {
        int idx = tid + it * 256;
        int r = idx >> 4;
        int d4 = (idx & 15) * 4;
        int base = (d4 & 56) + ((d4 & 4) >> 2);
        float4 v = *(const float4*)&qg[(size_t)r * Ee + d4];
        Qs[r * QP + base + 0] = f2tf32f(v.x);
        Qs[r * QP + base + 2] = f2tf32f(v.y);
        Qs[r * QP + base + 4] = f2tf32f(v.z);
        Qs[r * QP + base + 6] = f2tf32f(v.w);
    }

    float o[2][4][4];
    float m_i[4], l_i[4];
    #pragma unroll
    for (int r4 = 0; r4 < 4; r4++) { m_i[r4] = -1e30f; l_i[r4] = 0.f; }
    #pragma unroll
    for (int mf = 0; mf < 2; mf++)
        #pragma unroll
        for (int nf = 0; nf < 4; nf++)
            #pragma unroll
            for (int e = 0; e < 4; e++) o[mf][nf][e] = 0.f;

    // P-store interleave base for this thread's column group offset (within ns+8nf)
    const int pbase = 4 * (lc & 1) + ((lc >> 1) & 1);

    for (int kt = 0; kt < Nn / 64; kt++) {
        const int k0 = kt * 64;
        __syncthreads();   // prior iter's P/V reads done (and Q fill on iter 0)

        // K tile -> KP (pair-interleaved rows), V tile -> Vs (natural)
        #pragma unroll
        for (int it = 0; it < 4; it++) {
            int idx = tid + it * 256;
            int r = idx >> 4;
            int d4 = (idx & 15) * 4;
            int base = (d4 & 56) + ((d4 & 4) >> 2);
            float4 kv = *(const float4*)&kg[(size_t)(k0 + r) * Ee + d4];
            KP[r * QP + base + 0] = f2tf32f(kv.x);
            KP[r * QP + base + 2] = f2tf32f(kv.y);
            KP[r * QP + base + 4] = f2tf32f(kv.z);
            KP[r * QP + base + 6] = f2tf32f(kv.w);
            float4 vv = *(const float4*)&vg[(size_t)(k0 + r) * Ee + d4];
            float4 tv;
            tv.x = f2tf32f(vv.x); tv.y = f2tf32f(vv.y); tv.z = f2tf32f(vv.z); tv.w = f2tf32f(vv.w);
            *(float4*)&Vs[r * VPIT + d4] = tv;
        }
        __syncthreads();

        // S accumulators initialized with bias (C-frag layout)
        float c[2][4][4];
        #pragma unroll
        for (int mf = 0; mf < 2; mf++) {
            #pragma unroll
            for (int nf = 0; nf < 4; nf++) {
                const float* bp = bg + (size_t)(ms + 16 * mf + lr) * Nn + k0 + ns + 8 * nf + 2 * lc;
                float2 t0 = *(const float2*)bp;
                float2 t1 = *(const float2*)(bp + 8 * Nn);
                c[mf][nf][0] = t0.x; c[mf][nf][1] = t0.y;
                c[mf][nf][2] = t1.x; c[mf][nf][3] = t1.y;
            }
        }

        // S = Q K^T  (paired LDS.64 fragment loads)
        #pragma unroll
        for (int ks = 0; ks < 8; ks++) {
            int d0 = ks * 8;
            uint32_t af[2][4], bf[4][2];
            #pragma unroll
            for (int mf = 0; mf < 2; mf++) {
                uint2 q0v = *(const uint2*)&Qs[(ms + 16 * mf + lr) * QP + d0 + 2 * lc];
                uint2 q1v = *(const uint2*)&Qs[(ms + 16 * mf + lr + 8) * QP + d0 + 2 * lc];
                af[mf][0] = q0v.x; af[mf][2] = q0v.y;
                af[mf][1] = q1v.x; af[mf][3] = q1v.y;
            }
            #pragma unroll
            for (int nf = 0; nf < 4; nf++) {
                uint2 kb = *(const uint2*)&KP[(ns + 8 * nf + lr) * QP + d0 + 2 * lc];
                bf[nf][0] = kb.x; bf[nf][1] = kb.y;
            }
            #pragma unroll
            for (int mf = 0; mf < 2; mf++)
                #pragma unroll
                for (int nf = 0; nf < 4; nf++)
                    mma_tf32(c[mf][nf], af[mf], bf[nf]);
        }

        // Partial row max over this warp's 32 cols
        float pm[4];
        #pragma unroll
        for (int r4 = 0; r4 < 4; r4++) {
            int mf = r4 >> 1, hf = r4 & 1;
            float mx = fmaxf(c[mf][0][2 * hf], c[mf][0][2 * hf + 1]);
            #pragma unroll
            for (int nf = 1; nf < 4; nf++)
                mx = fmaxf(mx, fmaxf(c[mf][nf][2 * hf], c[mf][nf][2 * hf + 1]));
            mx = fmaxf(mx, __shfl_xor_sync(0xffffffffu, mx, 1));
            mx = fmaxf(mx, __shfl_xor_sync(0xffffffffu, mx, 2));
            pm[r4] = mx;
        }
        if (lc == 0) {
            #pragma unroll
            for (int r4 = 0; r4 < 4; r4++)
                stMax[(ms + lr + 8 * r4) * 2 + nsi] = pm[r4];
        }
        __syncthreads();   // stats visible; all warps done with K reads

        float alpha[4], psum[4];
        #pragma unroll
        for (int r4 = 0; r4 < 4; r4++) {
            float mo = stMax[(ms + lr + 8 * r4) * 2 + (1 - nsi)];
            float mt = fmaxf(pm[r4], mo);
            float mnew = fmaxf(m_i[r4], mt);
            alpha[r4] = __expf(m_i[r4] - mnew);
            m_i[r4] = mnew;
            psum[r4] = 0.f;
        }

        // exp, partial sums, store P (tf32-rounded, pair-interleaved) into KP
        #pragma unroll
        for (int mf = 0; mf < 2; mf++) {
            #pragma unroll
            for (int nf = 0; nf < 4; nf++) {
                #pragma unroll
                for (int e = 0; e < 4; e++) {
                    int r4 = mf * 2 + (e >> 1);
                    float p = __expf(c[mf][nf][e] - m_i[r4]);
                    psum[r4] += p;
                    c[mf][nf][e] = f2tf32f(p);
                }
                int pb = ns + 8 * nf + pbase;
                float* pr0 = KP + (ms + 16 * mf + lr) * QP + pb;
                float* pr1 = KP + (ms + 16 * mf + lr + 8) * QP + pb;
                pr0[0] = c[mf][nf][0]; pr0[2] = c[mf][nf][1];
                pr1[0] = c[mf][nf][2]; pr1[2] = c[mf][nf][3];
            }
        }
        #pragma unroll
        for (int r4 = 0; r4 < 4; r4++) {
            psum[r4] += __shfl_xor_sync(0xffffffffu, psum[r4], 1);
            psum[r4] += __shfl_xor_sync(0xffffffffu, psum[r4], 2);
        }
        if (lc == 0) {
            #pragma unroll
            for (int r4 = 0; r4 < 4; r4++)
                stSum[(ms + lr + 8 * r4) * 2 + nsi] = psum[r4];
        }
        __syncthreads();   // P fully written; sums visible

        #pragma unroll
        for (int r4 = 0; r4 < 4; r4++) {
            float so = stSum[(ms + lr + 8 * r4) * 2 + (1 - nsi)];
            l_i[r4] = l_i[r4] * alpha[r4] + psum[r4] + so;
        }
        #pragma unroll
        for (int mf = 0; mf < 2; mf++)
            #pragma unroll
            for (int nf = 0; nf < 4; nf++) {
                int r40 = mf * 2, r41 = mf * 2 + 1;
                o[mf][nf][0] *= alpha[r40];
                o[mf][nf][1] *= alpha[r40];
                o[mf][nf][2] *= alpha[r41];
                o[mf][nf][3] *= alpha[r41];
            }

        // O += P V   (A = P paired loads from KP; B = V scalar loads from Vs)
        #pragma unroll
        for (int ks = 0; ks < 8; ks++) {
            int kk0 = ks * 8;
            uint32_t af[2][4], bf[4][2];
            #pragma unroll
            for (int mf = 0; mf < 2; mf++) {
                uint2 p0 = *(const uint2*)&KP[(ms + 16 * mf + lr) * QP + kk0 + 2 * lc];
                uint2 p1 = *(const uint2*)&KP[(ms + 16 * mf + lr + 8) * QP + kk0 + 2 * lc];
                af[mf][0] = p0.x; af[mf][2] = p0.y;
                af[mf][1] = p1.x; af[mf][3] = p1.y;
            }
            #pragma unroll
            for (int nf = 0; nf < 4; nf++) {
                const float* vp = Vs + (kk0 + lc) * VPIT + ns + 8 * nf + lr;
                bf[nf][0] = __float_as_uint(vp[0]);
                bf[nf][1] = __float_as_uint(vp[4 * VPIT]);
            }
            #pragma unroll
            for (int mf = 0; mf < 2; mf++)
                #pragma unroll
                for (int nf = 0; nf < 4; nf++)
                    mma_tf32(o[mf][nf], af[mf], bf[nf]);
        }
    }

    // Normalize and write back
    float* og = g_attn + ((size_t)b * Nn + q0) * Ee + h * Dd;
    #pragma unroll
    for (int mf = 0; mf < 2; mf++) {
        float inv0 = 1.f / l_i[mf * 2];
        float inv1 = 1.f / l_i[mf * 2 + 1];
        int r0 = ms + 16 * mf + lr;
        #pragma unroll
        for (int nf = 0; nf < 4; nf++) {
            int cc = ns + 8 * nf + 2 * lc;
            *(float2*)&og[(size_t)r0 * Ee + cc] =
                make_float2(o[mf][nf][0] * inv0, o[mf][nf][1] * inv0);
            *(float2*)&og[(size_t)(r0 + 8) * Ee + cc] =
                make_float2(o[mf][nf][2] * inv1, o[mf][nf][3] * inv1);
        }
    }
}

// ---------------------------------------------------------------------------
extern "C" void kernel_launch(void* const* d_in, const int* in_sizes, int n_in,
                              void* d_out, int out_size)
{
    const float* query = (const float*)d_in[0];
    const float* abias = (const float*)d_in[1];
    const float* Wq = (const float*)d_in[2];
    const float* bq = (const float*)d_in[3];
    const float* Wk = (const float*)d_in[4];
    const float* bk = (const float*)d_in[5];
    const float* Wv = (const float*)d_in[6];
    const float* bv = (const float*)d_in[7];
    const float* Wo = (const float*)d_in[8];
    const float* bo = (const float*)d_in[9];
    float* out = (float*)d_out;

    float* gq; cudaGetSymbolAddress((void**)&gq, g_q);
    float* gk; cudaGetSymbolAddress((void**)&gk, g_k);
    float* gv; cudaGetSymbolAddress((void**)&gv, g_v);
    float* ga; cudaGetSymbolAddress((void**)&ga, g_attn);

    cudaFuncSetAttribute(attn_mma, cudaFuncAttributeMaxDynamicSharedMemorySize, ATTN_SMEM);

    const float scaling = 0.125f;  // Dd^-0.5

    dim3 gThreads(256);
    dim3 gGridProj(Ee / BN, Mtot / BM);     // (6, 64)

    gemm_mma<<<gGridProj, gThreads>>>(query, Wq, bq, gq, Mtot, Ee, Ee, scaling);
    gemm_mma<<<gGridProj, gThreads>>>(query, Wk, bk, gk, Mtot, Ee, Ee, 1.0f);
    gemm_mma<<<gGridProj, gThreads>>>(query, Wv, bv, gv, Mtot, Ee, Ee, 1.0f);

    dim3 aGrid(Nn / 128, Hh, Bb);           // (8, 12, 8)
    attn_mma<<<aGrid, gThreads, ATTN_SMEM>>>(abias);

    gemm_mma<<<gGridProj, gThreads>>>(ga, Wo, bo, out, Mtot, Ee, Ee, 1.0f);
}